// round 3
// baseline (speedup 1.0000x reference)
#include <cuda_runtime.h>
#include <cstdint>

#define U_N   100000
#define I_N   50000
#define R_N   5
#define E_N   100000
#define K_N   4
#define D_N   16
#define RD_N  64
#define OUT_N 64
#define KF_N  2

// ---------------- device scratch ----------------
__device__ float g_norm_u[U_N];
__device__ float g_norm_i[I_N];
__device__ float g_ead[R_N * E_N];
__device__ float g_m[(size_t)R_N * E_N * 32];        // per edge: [0..15]=Rf_fwd, [16..31]=Rf_rev
__device__ float g_ufeat[U_N * D_N];
__device__ float g_ifeat[I_N * D_N];
__device__ float g_invn_u[R_N * U_N];
__device__ float g_invn_i[R_N * I_N];
__device__ float g_P_u[(size_t)R_N * U_N * D_N];     // user_h @ node_w_fwd
__device__ float g_P_i[(size_t)R_N * I_N * D_N];     // item_h @ node_w_rev

// ---------------- helpers ----------------
__device__ __forceinline__ float red16(float v) {
    v += __shfl_xor_sync(0xffffffffu, v, 1);
    v += __shfl_xor_sync(0xffffffffu, v, 2);
    v += __shfl_xor_sync(0xffffffffu, v, 4);
    v += __shfl_xor_sync(0xffffffffu, v, 8);
    return v;
}
__device__ __forceinline__ float red32(float v) {
    v = red16(v);
    v += __shfl_xor_sync(0xffffffffu, v, 16);
    return v;
}

// ---------------- kernel 0: zero accumulators ----------------
__global__ void zero_kernel() {
    int idx = blockIdx.x * 256 + threadIdx.x;
    if (idx < U_N)        g_norm_u[idx] = 0.f;
    if (idx < I_N)        g_norm_i[idx] = 0.f;
    if (idx < U_N * D_N)  g_ufeat[idx]  = 0.f;
    if (idx < I_N * D_N)  g_ifeat[idx]  = 0.f;
}

// ---------------- kernel A: per-node invnorm + node projection ----------------
__global__ __launch_bounds__(256) void precompute_kernel(
    const float* __restrict__ user_h, const float* __restrict__ item_h,
    const float* __restrict__ node_w_fwd, const float* __restrict__ node_w_rev)
{
    __shared__ float sw[256];
    const int r = blockIdx.y;
    const bool isU = (blockIdx.z == 0);
    const float* W = isU ? node_w_fwd : node_w_rev;
    if (threadIdx.x < 256) sw[threadIdx.x] = W[r * 256 + threadIdx.x];
    __syncthreads();

    const int N = isU ? U_N : I_N;
    const int n = blockIdx.x * 256 + threadIdx.x;
    if (n >= N) return;

    const float* h = (isU ? user_h : item_h) + ((size_t)r * N + n) * 16;
    float xs[16];
    const float4* h4 = (const float4*)h;
    float4 x0 = h4[0], x1 = h4[1], x2 = h4[2], x3 = h4[3];
    xs[0]=x0.x; xs[1]=x0.y; xs[2]=x0.z; xs[3]=x0.w;
    xs[4]=x1.x; xs[5]=x1.y; xs[6]=x1.z; xs[7]=x1.w;
    xs[8]=x2.x; xs[9]=x2.y; xs[10]=x2.z; xs[11]=x2.w;
    xs[12]=x3.x; xs[13]=x3.y; xs[14]=x3.z; xs[15]=x3.w;

    float ss = 0.f;
#pragma unroll
    for (int j = 0; j < 16; j++) ss = fmaf(xs[j], xs[j], ss);
    float invn = rsqrtf(ss);
    if (isU) g_invn_u[(size_t)r * U_N + n] = invn;
    else     g_invn_i[(size_t)r * I_N + n] = invn;

    float4 a0 = {0,0,0,0}, a1 = {0,0,0,0}, a2 = {0,0,0,0}, a3 = {0,0,0,0};
    const float4* sw4 = (const float4*)sw;
#pragma unroll
    for (int j = 0; j < 16; j++) {
        float xv = xs[j];
        float4 w0 = sw4[j*4+0], w1 = sw4[j*4+1], w2 = sw4[j*4+2], w3 = sw4[j*4+3];
        a0.x = fmaf(xv, w0.x, a0.x); a0.y = fmaf(xv, w0.y, a0.y);
        a0.z = fmaf(xv, w0.z, a0.z); a0.w = fmaf(xv, w0.w, a0.w);
        a1.x = fmaf(xv, w1.x, a1.x); a1.y = fmaf(xv, w1.y, a1.y);
        a1.z = fmaf(xv, w1.z, a1.z); a1.w = fmaf(xv, w1.w, a1.w);
        a2.x = fmaf(xv, w2.x, a2.x); a2.y = fmaf(xv, w2.y, a2.y);
        a2.z = fmaf(xv, w2.z, a2.z); a2.w = fmaf(xv, w2.w, a2.w);
        a3.x = fmaf(xv, w3.x, a3.x); a3.y = fmaf(xv, w3.y, a3.y);
        a3.z = fmaf(xv, w3.z, a3.z); a3.w = fmaf(xv, w3.w, a3.w);
    }
    float4* P = (float4*)((isU ? g_P_u : g_P_i) + ((size_t)r * N + n) * 16);
    P[0] = a0; P[1] = a1; P[2] = a2; P[3] = a3;
}

// ---------------- kernel 1: per-edge ead + fused review projection ----------------
// grid: (E/8, R), block 256, one warp per edge.
// smem: proto[256] + smW[64*33] (combined [W_rf | W_rr], layout [j][o], stride 33
//       -> lane reads smW[j*33+lane]: bank=(j+lane)%32, conflict-free)
__global__ __launch_bounds__(256) void phase1_kernel(
    const float* __restrict__ user_h,     const float* __restrict__ item_h,
    const float* __restrict__ user_hsum,  const float* __restrict__ item_hsum,
    const float* __restrict__ review_feat,
    const float* __restrict__ prototypes, const float* __restrict__ eta,
    const float* __restrict__ review_w_fwd, const float* __restrict__ review_w_rev,
    const int*   __restrict__ rows,       const int*   __restrict__ cols)
{
    __shared__ float sm[256 + 64 * 33];
    float* smW = sm + 256;
    const int r = blockIdx.y;
    if (threadIdx.x < 256) sm[threadIdx.x] = prototypes[threadIdx.x];
    for (int i = threadIdx.x; i < 2048; i += 256) {
        int o = i & 31, j = i >> 5;
        float w = (o < 16) ? review_w_fwd[r * 1024 + j * 16 + o]
                           : review_w_rev[r * 1024 + j * 16 + (o - 16)];
        smW[j * 33 + o] = w;
    }
    __syncthreads();

    const int lane = threadIdx.x & 31;
    const int warp = threadIdx.x >> 5;
    const int e = blockIdx.x * 8 + warp;
    if (e >= E_N) return;

    const size_t idx = (size_t)r * E_N + e;
    const int row = rows[idx];
    const int col = cols[idx];

    // node dot: lanes 0-15 user dims, 16-31 item dims
    const int dh = lane & 15;
    float hval;
    if (lane < 16) hval = user_h[((size_t)r * U_N + row) * 16 + dh];
    else           hval = item_h[((size_t)r * I_N + col) * 16 + dh];
    float othv = __shfl_xor_sync(0xffffffffu, hval, 16);
    float dot = red16(hval * othv);
    float invnu = g_invn_u[(size_t)r * U_N + row];
    float invni = g_invn_i[(size_t)r * I_N + col];
    float sim_k = 2.0f * dot * invnu * invni;

    // sim_all over K=4
    const float* uh = user_hsum + ((size_t)r * U_N + row) * 64;
    const float* ih = item_hsum + ((size_t)r * I_N + col) * 64;
    float p1 = red16(uh[lane] * ih[lane]);
    float p2 = red16(uh[lane + 32] * ih[lane + 32]);
    float eh = __expf(2.0f * p1) + __expf(2.0f * p2);
    float Ssim = eh + __shfl_xor_sync(0xffffffffu, eh, 16);
    float exp_sim = __expf(sim_k) / Ssim;

    // review row (streaming; 8 coalesced 128B segments)
    const float* rf = review_feat + idx * 256;
    float rfa0 = __ldcs(rf + lane),       rfb0 = __ldcs(rf + 32 + lane);
    float rfa1 = __ldcs(rf + 64 + lane),  rfb1 = __ldcs(rf + 96 + lane);
    float rfa2 = __ldcs(rf + 128 + lane), rfb2 = __ldcs(rf + 160 + lane);
    float rfa3 = __ldcs(rf + 192 + lane), rfb3 = __ldcs(rf + 224 + lane);

    float ad0 = red32(fmaf(rfa0, sm[lane],       rfb0 * sm[32 + lane]));
    float ad1 = red32(fmaf(rfa1, sm[64 + lane],  rfb1 * sm[96 + lane]));
    float ad2 = red32(fmaf(rfa2, sm[128 + lane], rfb2 * sm[160 + lane]));
    float ad3 = red32(fmaf(rfa3, sm[192 + lane], rfb3 * sm[224 + lane]));

    float Sad = __expf(2.0f * ad0) + __expf(2.0f * ad1) +
                __expf(2.0f * ad2) + __expf(2.0f * ad3);
    float ead = __expf(2.0f * ad2) / Sad;                  // KF = 2

    float g = 1.0f / (1.0f + __expf(-eta[idx]));
    ead = g * ead + (1.0f - g) * exp_sim;

    if (lane == 0) {
        g_ead[idx] = ead;
        atomicAdd(&g_norm_u[row], ead);
        atomicAdd(&g_norm_i[col], ead);
    }

    // fused review projection: out[o=lane] = sum_j rf_k[j] * Wc[j][o]
    // rf_k[j] lives in rfa2 (j=lane) and rfb2 (j=32+lane) across the warp.
    float acc = 0.f;
#pragma unroll
    for (int j = 0; j < 32; j++) {
        float v = __shfl_sync(0xffffffffu, rfa2, j);
        acc = fmaf(v, smW[j * 33 + lane], acc);
    }
#pragma unroll
    for (int j = 0; j < 32; j++) {
        float v = __shfl_sync(0xffffffffu, rfb2, j);
        acc = fmaf(v, smW[(j + 32) * 33 + lane], acc);
    }
    g_m[idx * 32 + lane] = acc;   // one coalesced 128B store per warp
}

// ---------------- kernel 2: weight + gather P + scatter ----------------
__global__ __launch_bounds__(256) void phase2_kernel(
    const int* __restrict__ rows, const int* __restrict__ cols,
    float* __restrict__ int_dist_out)
{
    const int lane = threadIdx.x & 31;
    const int warp = threadIdx.x >> 5;
    const int e = blockIdx.x * 8 + warp;
    if (e >= E_N) return;
    const int r = blockIdx.y;
    const size_t idx = (size_t)r * E_N + e;

    const int row = rows[idx];
    const int col = cols[idx];
    const float ead = g_ead[idx];
    const float w = ead * rsqrtf(g_norm_u[row] * g_norm_i[col]);
    if (lane == 0) int_dist_out[idx] = w;

    float p;
    if (lane < 16) p = g_P_u[((size_t)r * U_N + row) * 16 + lane];
    else           p = g_P_i[((size_t)r * I_N + col) * 16 + (lane - 16)];
    const float mv = (g_m[idx * 32 + lane] + p) * w;
    if (lane < 16) atomicAdd(&g_ifeat[col * 16 + lane], mv);          // m_fwd -> ifeat[col]
    else           atomicAdd(&g_ufeat[row * 16 + (lane - 16)], mv);   // m_rev -> ufeat[row]
}

// ---------------- kernel 3: leaky + FC, weights in registers ----------------
#define NB_U ((U_N + 63) / 64)
#define NB_I ((I_N + 63) / 64)
__global__ __launch_bounds__(256) void fc_kernel(
    const float* __restrict__ ufc_w, const float* __restrict__ ufc_b,
    const float* __restrict__ ifc_w, const float* __restrict__ ifc_b,
    float* __restrict__ out)
{
    __shared__ float smx[64 * 17];
    const int tid = threadIdx.x;
    const bool isU = (blockIdx.x < NB_U);
    const int nb = (isU ? blockIdx.x : (blockIdx.x - NB_U)) * 64;
    const int N = isU ? U_N : I_N;
    const float* feat = isU ? g_ufeat : g_ifeat;
    const float* W = isU ? ufc_w : ifc_w;
    const float* B = isU ? ufc_b : ifc_b;
    float* outp = out + (isU ? 0 : (size_t)U_N * 64);

    for (int i = tid; i < 1024; i += 256) {
        int n = i >> 4, j = i & 15;
        int ng = nb + n;
        float x = (ng < N) ? feat[ng * 16 + j] : 0.f;
        x = (x >= 0.f) ? x : 0.1f * x;
        smx[n * 17 + j] = x;
    }
    __syncthreads();

    const int o = tid & 63;
    const int g = tid >> 6;
    float wr[16];
#pragma unroll
    for (int j = 0; j < 16; j++) wr[j] = W[j * 64 + o];
    const float b = B[o];

#pragma unroll
    for (int i = 0; i < 16; i++) {
        int n = g + i * 4;
        int ng = nb + n;
        if (ng < N) {
            float acc = b;
#pragma unroll
            for (int j = 0; j < 16; j++) acc = fmaf(smx[n * 17 + j], wr[j], acc);
            outp[(size_t)ng * 64 + o] = acc;
        }
    }
}

// ---------------- launch ----------------
extern "C" void kernel_launch(void* const* d_in, const int* in_sizes, int n_in,
                              void* d_out, int out_size)
{
    const float* user_h       = (const float*)d_in[0];
    const float* item_h       = (const float*)d_in[1];
    const float* user_hsum    = (const float*)d_in[2];
    const float* item_hsum    = (const float*)d_in[3];
    const float* review_feat  = (const float*)d_in[4];
    const float* prototypes   = (const float*)d_in[5];
    const float* eta          = (const float*)d_in[6];
    const float* node_w_fwd   = (const float*)d_in[7];
    const float* node_w_rev   = (const float*)d_in[8];
    const float* review_w_fwd = (const float*)d_in[9];
    const float* review_w_rev = (const float*)d_in[10];
    const float* ufc_w        = (const float*)d_in[11];
    const float* ufc_b        = (const float*)d_in[12];
    const float* ifc_w        = (const float*)d_in[13];
    const float* ifc_b        = (const float*)d_in[14];
    const int*   rows         = (const int*)d_in[15];
    const int*   cols         = (const int*)d_in[16];
    float* out = (float*)d_out;

    zero_kernel<<<(U_N * D_N + 255) / 256, 256>>>();

    dim3 pgrid((U_N + 255) / 256, R_N, 2);
    precompute_kernel<<<pgrid, 256>>>(user_h, item_h, node_w_fwd, node_w_rev);

    dim3 egrid(E_N / 8, R_N);
    phase1_kernel<<<egrid, 256>>>(user_h, item_h, user_hsum, item_hsum,
                                  review_feat, prototypes, eta,
                                  review_w_fwd, review_w_rev, rows, cols);

    phase2_kernel<<<egrid, 256>>>(rows, cols, out + (size_t)(U_N + I_N) * OUT_N);

    fc_kernel<<<NB_U + NB_I, 256>>>(ufc_w, ufc_b, ifc_w, ifc_b, out);
}

// round 4
// speedup vs baseline: 1.5658x; 1.5658x over previous
#include <cuda_runtime.h>
#include <cstdint>

#define U_N   100000
#define I_N   50000
#define R_N   5
#define E_N   100000
#define K_N   4
#define D_N   16
#define RD_N  64
#define OUT_N 64
#define KF_N  2

// ---------------- device scratch ----------------
__device__ float g_norm_u[U_N];
__device__ float g_norm_i[I_N];
__device__ float g_ead[R_N * E_N];
__device__ float g_m[(size_t)R_N * E_N * 32];        // per edge: [0..15]=Rf_fwd, [16..31]=Rf_rev
__device__ float g_ufeat[U_N * D_N];
__device__ float g_ifeat[I_N * D_N];
__device__ float g_invn_u[R_N * U_N];
__device__ float g_invn_i[R_N * I_N];
__device__ float g_P_u[(size_t)R_N * U_N * D_N];     // user_h @ node_w_fwd
__device__ float g_P_i[(size_t)R_N * I_N * D_N];     // item_h @ node_w_rev

// ---------------- helpers ----------------
__device__ __forceinline__ float red16(float v) {
    v += __shfl_xor_sync(0xffffffffu, v, 1);
    v += __shfl_xor_sync(0xffffffffu, v, 2);
    v += __shfl_xor_sync(0xffffffffu, v, 4);
    v += __shfl_xor_sync(0xffffffffu, v, 8);
    return v;
}
__device__ __forceinline__ float red32(float v) {
    v = red16(v);
    v += __shfl_xor_sync(0xffffffffu, v, 16);
    return v;
}
__device__ __forceinline__ void red_v4(float* addr, float4 v) {
    asm volatile("red.global.add.v4.f32 [%0], {%1, %2, %3, %4};"
                 :: "l"(addr), "f"(v.x), "f"(v.y), "f"(v.z), "f"(v.w)
                 : "memory");
}

// ---------------- kernel 0: zero accumulators ----------------
__global__ void zero_kernel() {
    int idx = blockIdx.x * 256 + threadIdx.x;
    if (idx < U_N)        g_norm_u[idx] = 0.f;
    if (idx < I_N)        g_norm_i[idx] = 0.f;
    if (idx < U_N * D_N)  g_ufeat[idx]  = 0.f;
    if (idx < I_N * D_N)  g_ifeat[idx]  = 0.f;
}

// ---------------- kernel A: per-node invnorm + node projection ----------------
__global__ __launch_bounds__(256) void precompute_kernel(
    const float* __restrict__ user_h, const float* __restrict__ item_h,
    const float* __restrict__ node_w_fwd, const float* __restrict__ node_w_rev)
{
    __shared__ float sw[256];
    const int r = blockIdx.y;
    const bool isU = (blockIdx.z == 0);
    const float* W = isU ? node_w_fwd : node_w_rev;
    if (threadIdx.x < 256) sw[threadIdx.x] = W[r * 256 + threadIdx.x];
    __syncthreads();

    const int N = isU ? U_N : I_N;
    const int n = blockIdx.x * 256 + threadIdx.x;
    if (n >= N) return;

    const float* h = (isU ? user_h : item_h) + ((size_t)r * N + n) * 16;
    float xs[16];
    const float4* h4 = (const float4*)h;
    float4 x0 = h4[0], x1 = h4[1], x2 = h4[2], x3 = h4[3];
    xs[0]=x0.x; xs[1]=x0.y; xs[2]=x0.z; xs[3]=x0.w;
    xs[4]=x1.x; xs[5]=x1.y; xs[6]=x1.z; xs[7]=x1.w;
    xs[8]=x2.x; xs[9]=x2.y; xs[10]=x2.z; xs[11]=x2.w;
    xs[12]=x3.x; xs[13]=x3.y; xs[14]=x3.z; xs[15]=x3.w;

    float ss = 0.f;
#pragma unroll
    for (int j = 0; j < 16; j++) ss = fmaf(xs[j], xs[j], ss);
    float invn = rsqrtf(ss);
    if (isU) g_invn_u[(size_t)r * U_N + n] = invn;
    else     g_invn_i[(size_t)r * I_N + n] = invn;

    float4 a0 = {0,0,0,0}, a1 = {0,0,0,0}, a2 = {0,0,0,0}, a3 = {0,0,0,0};
    const float4* sw4 = (const float4*)sw;
#pragma unroll
    for (int j = 0; j < 16; j++) {
        float xv = xs[j];
        float4 w0 = sw4[j*4+0], w1 = sw4[j*4+1], w2 = sw4[j*4+2], w3 = sw4[j*4+3];
        a0.x = fmaf(xv, w0.x, a0.x); a0.y = fmaf(xv, w0.y, a0.y);
        a0.z = fmaf(xv, w0.z, a0.z); a0.w = fmaf(xv, w0.w, a0.w);
        a1.x = fmaf(xv, w1.x, a1.x); a1.y = fmaf(xv, w1.y, a1.y);
        a1.z = fmaf(xv, w1.z, a1.z); a1.w = fmaf(xv, w1.w, a1.w);
        a2.x = fmaf(xv, w2.x, a2.x); a2.y = fmaf(xv, w2.y, a2.y);
        a2.z = fmaf(xv, w2.z, a2.z); a2.w = fmaf(xv, w2.w, a2.w);
        a3.x = fmaf(xv, w3.x, a3.x); a3.y = fmaf(xv, w3.y, a3.y);
        a3.z = fmaf(xv, w3.z, a3.z); a3.w = fmaf(xv, w3.w, a3.w);
    }
    float4* P = (float4*)((isU ? g_P_u : g_P_i) + ((size_t)r * N + n) * 16);
    P[0] = a0; P[1] = a1; P[2] = a2; P[3] = a3;
}

// ---------------- kernel 1: per-edge ead only (R2 structure) ----------------
__global__ __launch_bounds__(256) void phase1_kernel(
    const float* __restrict__ user_h,     const float* __restrict__ item_h,
    const float* __restrict__ user_hsum,  const float* __restrict__ item_hsum,
    const float* __restrict__ review_feat,
    const float* __restrict__ prototypes, const float* __restrict__ eta,
    const int*   __restrict__ rows,       const int*   __restrict__ cols)
{
    __shared__ float sm[256];
    const int r = blockIdx.y;
    if (threadIdx.x < 256) sm[threadIdx.x] = prototypes[threadIdx.x];
    __syncthreads();

    const int lane = threadIdx.x & 31;
    const int warp = threadIdx.x >> 5;
    const int e = blockIdx.x * 8 + warp;
    if (e >= E_N) return;

    const size_t idx = (size_t)r * E_N + e;
    const int row = rows[idx];
    const int col = cols[idx];

    const int dh = lane & 15;
    float hval;
    if (lane < 16) hval = user_h[((size_t)r * U_N + row) * 16 + dh];
    else           hval = item_h[((size_t)r * I_N + col) * 16 + dh];
    float othv = __shfl_xor_sync(0xffffffffu, hval, 16);
    float dot = red16(hval * othv);
    float invnu = g_invn_u[(size_t)r * U_N + row];
    float invni = g_invn_i[(size_t)r * I_N + col];
    float sim_k = 2.0f * dot * invnu * invni;

    const float* uh = user_hsum + ((size_t)r * U_N + row) * 64;
    const float* ih = item_hsum + ((size_t)r * I_N + col) * 64;
    float p1 = red16(uh[lane] * ih[lane]);
    float p2 = red16(uh[lane + 32] * ih[lane + 32]);
    float eh = __expf(2.0f * p1) + __expf(2.0f * p2);
    float Ssim = eh + __shfl_xor_sync(0xffffffffu, eh, 16);
    float exp_sim = __expf(sim_k) / Ssim;

    const float* rf = review_feat + idx * 256;
    float ad0 = red32(fmaf(__ldcs(rf + lane),       sm[lane],       __ldcs(rf + 32 + lane)  * sm[32 + lane]));
    float ad1 = red32(fmaf(__ldcs(rf + 64 + lane),  sm[64 + lane],  __ldcs(rf + 96 + lane)  * sm[96 + lane]));
    float ad2 = red32(fmaf(__ldcs(rf + 128 + lane), sm[128 + lane], __ldcs(rf + 160 + lane) * sm[160 + lane]));
    float ad3 = red32(fmaf(__ldcs(rf + 192 + lane), sm[192 + lane], __ldcs(rf + 224 + lane) * sm[224 + lane]));

    float Sad = __expf(2.0f * ad0) + __expf(2.0f * ad1) +
                __expf(2.0f * ad2) + __expf(2.0f * ad3);
    float ead = __expf(2.0f * ad2) / Sad;                  // KF = 2

    float g = 1.0f / (1.0f + __expf(-eta[idx]));
    ead = g * ead + (1.0f - g) * exp_sim;

    if (lane == 0) {
        g_ead[idx] = ead;
        atomicAdd(&g_norm_u[row], ead);
        atomicAdd(&g_norm_i[col], ead);
    }
}

// ---------------- kernel B: review projection GEMM (16 edges/warp) ----------------
// Rf[e][o] = sum_j rf_k[e][j] * Wc[j][o], Wc = [review_w_fwd | review_w_rev] (64x32)
// grid: (ceil(E/128), R), block 256. Warp owns 16 edges x 32 outs.
__global__ __launch_bounds__(256) void rproj_kernel(
    const float* __restrict__ review_feat,
    const float* __restrict__ review_w_fwd, const float* __restrict__ review_w_rev)
{
    __shared__ float  smWT[32 * 68];      // [o][j], row stride 68 floats
    __shared__ float4 smrf[128 * 17];     // [e][jq], row stride 17 float4
    const int r = blockIdx.y;
    const int tid = threadIdx.x;

    for (int i = tid; i < 2048; i += 256) {
        int o = i & 31, j = i >> 5;
        float w = (o < 16) ? review_w_fwd[r * 1024 + j * 16 + o]
                           : review_w_rev[r * 1024 + j * 16 + (o - 16)];
        smWT[o * 68 + j] = w;
    }

    const int e0 = blockIdx.x * 128;
    for (int i = tid; i < 2048; i += 256) {
        int e = i >> 4, jq = i & 15;
        int eg = e0 + e;
        float4 v = {0,0,0,0};
        if (eg < E_N)
            v = *(const float4*)(review_feat + ((size_t)r * E_N + eg) * 256 + 128 + jq * 4);
        smrf[e * 17 + jq] = v;
    }
    __syncthreads();

    const int lane = tid & 31;
    const int warp = tid >> 5;
    const int eb = warp * 16;
    float acc[16];
#pragma unroll
    for (int ee = 0; ee < 16; ee++) acc[ee] = 0.f;
    const float4* wt4 = (const float4*)(smWT + lane * 68);
#pragma unroll
    for (int jq = 0; jq < 16; jq++) {
        float4 wv = wt4[jq];
#pragma unroll
        for (int ee = 0; ee < 16; ee++) {
            float4 rv = smrf[(eb + ee) * 17 + jq];
            acc[ee] = fmaf(rv.x, wv.x, acc[ee]);
            acc[ee] = fmaf(rv.y, wv.y, acc[ee]);
            acc[ee] = fmaf(rv.z, wv.z, acc[ee]);
            acc[ee] = fmaf(rv.w, wv.w, acc[ee]);
        }
    }
#pragma unroll
    for (int ee = 0; ee < 16; ee++) {
        int eg = e0 + eb + ee;
        if (eg < E_N)
            g_m[((size_t)r * E_N + eg) * 32 + lane] = acc[ee];
    }
}

// ---------------- kernel 2: weight + gather P + vectorized RED scatter ----------------
// 8 threads per edge; thread q handles 4 dims. q<4: fwd->ifeat, q>=4: rev->ufeat.
__global__ __launch_bounds__(256) void phase2_kernel(
    const int* __restrict__ rows, const int* __restrict__ cols,
    float* __restrict__ int_dist_out)
{
    const int t = blockIdx.x * 256 + threadIdx.x;
    const int e = t >> 3;
    const int q = t & 7;
    if (e >= E_N) return;
    const int r = blockIdx.y;
    const size_t idx = (size_t)r * E_N + e;

    const int row = rows[idx];
    const int col = cols[idx];
    const float ead = g_ead[idx];
    const float w = ead * rsqrtf(g_norm_u[row] * g_norm_i[col]);
    if (q == 0) int_dist_out[idx] = w;

    float4 m4, p4;
    float* dest;
    if (q < 4) {
        m4 = *(const float4*)(g_m + idx * 32 + q * 4);
        p4 = *(const float4*)(g_P_u + ((size_t)r * U_N + row) * 16 + q * 4);
        dest = g_ifeat + col * 16 + q * 4;
    } else {
        const int qq = q - 4;
        m4 = *(const float4*)(g_m + idx * 32 + 16 + qq * 4);
        p4 = *(const float4*)(g_P_i + ((size_t)r * I_N + col) * 16 + qq * 4);
        dest = g_ufeat + row * 16 + qq * 4;
    }
    float4 mv;
    mv.x = (m4.x + p4.x) * w;
    mv.y = (m4.y + p4.y) * w;
    mv.z = (m4.z + p4.z) * w;
    mv.w = (m4.w + p4.w) * w;
    red_v4(dest, mv);
}

// ---------------- kernel 3: leaky + FC, weights in registers ----------------
#define NB_U ((U_N + 63) / 64)
#define NB_I ((I_N + 63) / 64)
__global__ __launch_bounds__(256) void fc_kernel(
    const float* __restrict__ ufc_w, const float* __restrict__ ufc_b,
    const float* __restrict__ ifc_w, const float* __restrict__ ifc_b,
    float* __restrict__ out)
{
    __shared__ float smx[64 * 17];
    const int tid = threadIdx.x;
    const bool isU = (blockIdx.x < NB_U);
    const int nb = (isU ? blockIdx.x : (blockIdx.x - NB_U)) * 64;
    const int N = isU ? U_N : I_N;
    const float* feat = isU ? g_ufeat : g_ifeat;
    const float* W = isU ? ufc_w : ifc_w;
    const float* B = isU ? ufc_b : ifc_b;
    float* outp = out + (isU ? 0 : (size_t)U_N * 64);

    for (int i = tid; i < 1024; i += 256) {
        int n = i >> 4, j = i & 15;
        int ng = nb + n;
        float x = (ng < N) ? feat[ng * 16 + j] : 0.f;
        x = (x >= 0.f) ? x : 0.1f * x;
        smx[n * 17 + j] = x;
    }
    __syncthreads();

    const int o = tid & 63;
    const int g = tid >> 6;
    float wr[16];
#pragma unroll
    for (int j = 0; j < 16; j++) wr[j] = W[j * 64 + o];
    const float b = B[o];

#pragma unroll
    for (int i = 0; i < 16; i++) {
        int n = g + i * 4;
        int ng = nb + n;
        if (ng < N) {
            float acc = b;
#pragma unroll
            for (int j = 0; j < 16; j++) acc = fmaf(smx[n * 17 + j], wr[j], acc);
            outp[(size_t)ng * 64 + o] = acc;
        }
    }
}

// ---------------- launch ----------------
extern "C" void kernel_launch(void* const* d_in, const int* in_sizes, int n_in,
                              void* d_out, int out_size)
{
    const float* user_h       = (const float*)d_in[0];
    const float* item_h       = (const float*)d_in[1];
    const float* user_hsum    = (const float*)d_in[2];
    const float* item_hsum    = (const float*)d_in[3];
    const float* review_feat  = (const float*)d_in[4];
    const float* prototypes   = (const float*)d_in[5];
    const float* eta          = (const float*)d_in[6];
    const float* node_w_fwd   = (const float*)d_in[7];
    const float* node_w_rev   = (const float*)d_in[8];
    const float* review_w_fwd = (const float*)d_in[9];
    const float* review_w_rev = (const float*)d_in[10];
    const float* ufc_w        = (const float*)d_in[11];
    const float* ufc_b        = (const float*)d_in[12];
    const float* ifc_w        = (const float*)d_in[13];
    const float* ifc_b        = (const float*)d_in[14];
    const int*   rows         = (const int*)d_in[15];
    const int*   cols         = (const int*)d_in[16];
    float* out = (float*)d_out;

    zero_kernel<<<(U_N * D_N + 255) / 256, 256>>>();

    dim3 pgrid((U_N + 255) / 256, R_N, 2);
    precompute_kernel<<<pgrid, 256>>>(user_h, item_h, node_w_fwd, node_w_rev);

    dim3 egrid(E_N / 8, R_N);
    phase1_kernel<<<egrid, 256>>>(user_h, item_h, user_hsum, item_hsum,
                                  review_feat, prototypes, eta, rows, cols);

    dim3 bgrid((E_N + 127) / 128, R_N);
    rproj_kernel<<<bgrid, 256>>>(review_feat, review_w_fwd, review_w_rev);

    dim3 p2grid((E_N * 8 + 255) / 256, R_N);
    phase2_kernel<<<p2grid, 256>>>(rows, cols, out + (size_t)(U_N + I_N) * OUT_N);

    fc_kernel<<<NB_U + NB_I, 256>>>(ufc_w, ufc_b, ifc_w, ifc_b, out);
}